// round 10
// baseline (speedup 1.0000x reference)
#include <cuda_runtime.h>
#include <cuda_bf16.h>

// CASSI forward A^T(A(x)); coded aperture is band-broadcast (phi[l]==phi2d):
//   y2[b,m,j]    = sum_{l : 0<=j-2l<N} x[b,l,m,j-2l]*phi2d[m,j-2l]
//   out[b,l,m,n] = phi2d[m,n] * y2[b,m,n+2l]
// One CTA per (b,m) row. L=28, M=N=256 (compile-time), STRIDE=2, n_out=310.
//
// R10 = R9 + 7 CTAs/SM (smem 31.25KB*7 = 218.75KB <= ~227KB) and all-constant
// geometry (M folded) to hold regs <= 36 for the 7-CTA occupancy target.

#define LBANDS 28
#define NCOLS  256
#define NC4    (NCOLS / 4)                        // 64 float4 per row
#define NOUT   (NCOLS + 2 * (LBANDS - 1))         // 310
#define THREADS 256
#define MNFIX  (NCOLS * NCOLS)                    // elems per band (M==N==256)
#define BAND4  (MNFIX / 4)                        // float4 stride between bands

__global__ __launch_bounds__(THREADS, 7)
void cassi_kernel(const float4* __restrict__ x4,
                  const float4* __restrict__ phi4,
                  float4* __restrict__ out4,
                  int LMN4 /* L*M*N/4 */)
{
    __shared__ float prod[LBANDS * NCOLS];   // 28 KB
    __shared__ float y2 [320];
    __shared__ float y2s[320];               // y2s[j] == y2[j+2]
    float4* prod4 = reinterpret_cast<float4*>(prod);

    const int m   = blockIdx.x;
    const int b   = blockIdx.y;
    const int tid = threadIdx.x;

    const int lsub = tid >> 6;        // 0..3, uniform per warp-pair
    const int c    = tid & 63;        // float4 column 0..63

    const int xrow4 = b * LMN4 + m * NC4;        // x/out row base (float4 units)

    // phi2d row element for this thread's 4 columns — band-independent.
    const float4 pv = phi4[m * NC4 + c];

    // ---- phase 1: prod = x*phi -> smem (LDG.128 + STS.128 per band) ----
    {
        int xo = xrow4 + lsub * BAND4 + c;
        int so = lsub * NC4 + c;
#pragma unroll
        for (int k = 0; k < LBANDS / 4; ++k) {
            const float4 xv = x4[xo];
            float4 pr;
            pr.x = xv.x * pv.x; pr.y = xv.y * pv.y;
            pr.z = xv.z * pv.z; pr.w = xv.w * pv.w;
            prod4[so] = pr;
            xo += 4 * BAND4; so += 4 * NC4;
        }
    }
    __syncthreads();

    // ---- phase 2: y2[j],y2[j+1] (j even) via aligned LDS.64 ----
    // For even j: lmin/lmax identical for j and j+1; prod address 2-aligned.
    {
        const int j = tid << 1;                   // 0,2,...,510
        if (j < NOUT) {
            const int lmin = (j >= NCOLS) ? ((j - (NCOLS - 2)) >> 1) : 0;
            const int jh   = j >> 1;
            const int lmax = jh < (LBANDS - 1) ? jh : (LBANDS - 1);
            float sx = 0.0f, sy = 0.0f;
            const float* pb = prod + j;
            for (int l = lmin; l <= lmax; ++l) {
                const float2 p =
                    *reinterpret_cast<const float2*>(pb + l * (NCOLS - 2));
                sx += p.x; sy += p.y;
            }
            y2[j]     = sx;
            y2[j + 1] = sy;
            if (j >= 2) {
                y2s[j - 2] = sx;
                y2s[j - 1] = sy;
            }
        }
    }
    __syncthreads();

    // ---- phase 3: out = phi * y2[n+2l]; phi from register, y2 via LDS.128 ----
    {
        // band l = 4k + lsub; parity of l == parity of lsub (warp-uniform)
        const float* ybase = (lsub & 1) ? y2s : y2;
        // aligned float4 index covering y2[4c + 2l] (shift folded into y2s)
        int yo4 = ((c << 2) + 2 * lsub - ((lsub & 1) << 1)) >> 2;
        int oo  = xrow4 + lsub * BAND4 + c;
#pragma unroll
        for (int k = 0; k < LBANDS / 4; ++k) {
            const float4 yv = reinterpret_cast<const float4*>(ybase)[yo4];
            float4 ov;
            ov.x = pv.x * yv.x; ov.y = pv.y * yv.y;
            ov.z = pv.z * yv.z; ov.w = pv.w * yv.w;
            out4[oo] = ov;
            oo += 4 * BAND4;
            yo4 += 2;                      // 4 bands * stride 2 = 8 floats
        }
    }
}

extern "C" void kernel_launch(void* const* d_in, const int* in_sizes, int n_in,
                              void* d_out, int out_size)
{
    const float4* x4   = (const float4*)d_in[0];   // [B, L, M, N]
    const float4* phi4 = (const float4*)d_in[1];   // [L, M, N] (band-broadcast)
    float4* out4 = (float4*)d_out;

    const int LMN  = in_sizes[1];        // L*M*N
    const int B    = in_sizes[0] / LMN;  // batch
    const int LMN4 = LMN / 4;

    dim3 grid(NCOLS /* M */, B);
    cassi_kernel<<<grid, THREADS>>>(x4, phi4, out4, LMN4);
}

// round 11
// speedup vs baseline: 1.1478x; 1.1478x over previous
#include <cuda_runtime.h>
#include <cuda_bf16.h>

// CASSI forward A^T(A(x)); coded aperture is band-broadcast (phi[l]==phi2d):
//   y2[b,m,j]    = sum_{l : 0<=j-2l<N} x[b,l,m,j-2l]*phi2d[m,j-2l]
//   out[b,l,m,n] = phi2d[m,n] * y2[b,m,n+2l]
// One CTA per (b,m) row. L=28, M=N=256, STRIDE=2, n_out=310.
//
// R11 = R9 (6 CTAs/SM sweet spot: occ x MLP, per R3/R9/R10 sweep) +
//   - phase-2 fast path: even j in [54,254] has the constant band range 0..27
//     -> fully unrolled 28 independent LDS.64 (max smem MLP, no loop overhead)
//   - float2 STS for y2/y2s
//   - geometry constants folded (M==N==256)

#define LBANDS 28
#define NCOLS  256
#define NC4    (NCOLS / 4)                        // 64 float4 per row
#define NOUT   (NCOLS + 2 * (LBANDS - 1))         // 310
#define THREADS 256
#define MNFIX  (NCOLS * NCOLS)                    // elems per band
#define BAND4  (MNFIX / 4)                        // float4 stride between bands

__global__ __launch_bounds__(THREADS, 6)
void cassi_kernel(const float4* __restrict__ x4,
                  const float4* __restrict__ phi4,
                  float4* __restrict__ out4,
                  int LMN4 /* L*M*N/4 */)
{
    __shared__ float prod[LBANDS * NCOLS];   // 28 KB
    __shared__ float y2 [320];
    __shared__ float y2s[320];               // y2s[j] == y2[j+2]
    float4* prod4 = reinterpret_cast<float4*>(prod);

    const int m   = blockIdx.x;
    const int b   = blockIdx.y;
    const int tid = threadIdx.x;

    const int lsub = tid >> 6;        // 0..3, uniform per warp-pair
    const int c    = tid & 63;        // float4 column 0..63

    const int xrow4 = b * LMN4 + m * NC4;        // x/out row base (float4 units)

    // phi2d row element for this thread's 4 columns — band-independent.
    const float4 pv = phi4[m * NC4 + c];

    // ---- phase 1: prod = x*phi -> smem (LDG.128 + STS.128 per band) ----
    {
        int xo = xrow4 + lsub * BAND4 + c;
        int so = lsub * NC4 + c;
#pragma unroll
        for (int k = 0; k < LBANDS / 4; ++k) {
            const float4 xv = x4[xo];
            float4 pr;
            pr.x = xv.x * pv.x; pr.y = xv.y * pv.y;
            pr.z = xv.z * pv.z; pr.w = xv.w * pv.w;
            prod4[so] = pr;
            xo += 4 * BAND4; so += 4 * NC4;
        }
    }
    __syncthreads();

    // ---- phase 2: y2[j],y2[j+1] (j even) via aligned LDS.64 ----
    // Even j: lmin/lmax identical for j and j+1; prod address 2-aligned.
    // Fast path: j in [54,254] -> full constant range 0..27, fully unrolled.
    {
        const int j = tid << 1;                   // 0,2,...,510
        if (j < NOUT) {
            float sx = 0.0f, sy = 0.0f;
            const float* pb = prod + j;
            if (j >= 2 * (LBANDS - 1) && j < NCOLS) {
#pragma unroll
                for (int l = 0; l < LBANDS; ++l) {
                    const float2 p =
                        *reinterpret_cast<const float2*>(pb + l * (NCOLS - 2));
                    sx += p.x; sy += p.y;
                }
            } else {
                const int lmin = (j >= NCOLS) ? ((j - (NCOLS - 2)) >> 1) : 0;
                const int jh   = j >> 1;
                const int lmax = jh < (LBANDS - 1) ? jh : (LBANDS - 1);
                for (int l = lmin; l <= lmax; ++l) {
                    const float2 p =
                        *reinterpret_cast<const float2*>(pb + l * (NCOLS - 2));
                    sx += p.x; sy += p.y;
                }
            }
            *reinterpret_cast<float2*>(y2 + j) = make_float2(sx, sy);
            if (j >= 2)
                *reinterpret_cast<float2*>(y2s + j - 2) = make_float2(sx, sy);
        }
    }
    __syncthreads();

    // ---- phase 3: out = phi * y2[n+2l]; phi from register, y2 via LDS.128 ----
    {
        // band l = 4k + lsub; parity of l == parity of lsub (warp-uniform)
        const float* ybase = (lsub & 1) ? y2s : y2;
        // aligned float4 index covering y2[4c + 2l] (shift folded into y2s)
        int yo4 = ((c << 2) + 2 * lsub - ((lsub & 1) << 1)) >> 2;
        int oo  = xrow4 + lsub * BAND4 + c;
#pragma unroll
        for (int k = 0; k < LBANDS / 4; ++k) {
            const float4 yv = reinterpret_cast<const float4*>(ybase)[yo4];
            float4 ov;
            ov.x = pv.x * yv.x; ov.y = pv.y * yv.y;
            ov.z = pv.z * yv.z; ov.w = pv.w * yv.w;
            out4[oo] = ov;
            oo += 4 * BAND4;
            yo4 += 2;                      // 4 bands * stride 2 = 8 floats
        }
    }
}

extern "C" void kernel_launch(void* const* d_in, const int* in_sizes, int n_in,
                              void* d_out, int out_size)
{
    const float4* x4   = (const float4*)d_in[0];   // [B, L, M, N]
    const float4* phi4 = (const float4*)d_in[1];   // [L, M, N] (band-broadcast)
    float4* out4 = (float4*)d_out;

    const int LMN  = in_sizes[1];        // L*M*N
    const int B    = in_sizes[0] / LMN;  // batch
    const int LMN4 = LMN / 4;

    dim3 grid(NCOLS /* M */, B);
    cassi_kernel<<<grid, THREADS>>>(x4, phi4, out4, LMN4);
}